// round 10
// baseline (speedup 1.0000x reference)
#include <cuda_runtime.h>

// NCM R10: R9 + occupancy push. TPB=384 (12 warps/CTA, 3 warps/SMSP),
// warp tile 20 samples = 10 f32x2 pairs. Grid 148 (full chip), clamp tail.
// cp.async double-buffered weights, u prefetch, 1 barrier/node.

#define TPB    384
#define NBLK   148
#define NNODES 32
#define WPB    12          // warps per CTA
#define NP     10          // sample-pairs per warp
#define SPW    20          // samples per warp
#define SBMAX  (32768 - SPW)

typedef unsigned long long u64;
typedef unsigned int u32;

__device__ __forceinline__ u64 fma2(u64 a, u64 b, u64 c) {
    u64 d; asm("fma.rn.f32x2 %0,%1,%2,%3;" : "=l"(d) : "l"(a), "l"(b), "l"(c));
    return d;
}
__device__ __forceinline__ u64 dup2(float x) {
    u64 d; asm("mov.b64 %0,{%1,%1};" : "=l"(d) : "f"(x)); return d;
}
__device__ __forceinline__ void unpk(u64 a, float& lo, float& hi) {
    asm("mov.b64 {%0,%1},%2;" : "=f"(lo), "=f"(hi) : "l"(a));
}
__device__ __forceinline__ u64 pk(float lo, float hi) {
    u64 d; asm("mov.b64 %0,{%1,%2};" : "=l"(d) : "f"(lo), "f"(hi)); return d;
}
__device__ __forceinline__ u64 relu2(u64 a) {
    float lo, hi; unpk(a, lo, hi);
    return pk(fmaxf(lo, 0.0f), fmaxf(hi, 0.0f));
}
__device__ __forceinline__ void cpa16(u32 dst, const float* src) {
    asm volatile("cp.async.cg.shared.global [%0], [%1], 16;"
                 :: "r"(dst), "l"(src));
}

// per-buffer u64 offsets: W1 0 | W2 2560 | W3 4608 | B1 5120 | B2 5152 | B3 5184
#define BUFSZ 5192
// byte offsets inside buffer
#define BW2 20480
#define BW3 36864
#define BB1 40960
#define BB2 41216
#define BB3 41472
#define ACT (2 * BUFSZ)                 // 10384 u64
// per-warp acts: ring u64[NP][66] | h u64[NP][66] (u aliased into h cols 0..15)
#define ASTR 66
#define WARP_U64 (2 * NP * ASTR)        // 1320
#define SMEM_BYTES ((ACT + WPB * WARP_U64) * 8)   // 209792

__global__ void __launch_bounds__(TPB, 1) ncm_kernel(
    const float* __restrict__ u,
    const float* __restrict__ w_r1, const float* __restrict__ b_r1,
    const float* __restrict__ w_r2, const float* __restrict__ b_r2,
    const float* __restrict__ w_r3, const float* __restrict__ b_r3,
    const float* __restrict__ w_i1, const float* __restrict__ b_i1,
    const float* __restrict__ w_i2, const float* __restrict__ b_i2,
    const float* __restrict__ w_i3, const float* __restrict__ b_i3,
    float* __restrict__ out)
{
    extern __shared__ u64 sm[];

    const int tid = threadIdx.x;
    const int wp = tid >> 5, l = tid & 31;
    const int q8 = l & 7;    // L3: output dims (2q8, 2q8+1)
    const int g  = l >> 3;   // L3: pairs 4g..4g+3 (clamped to NP-1)

    u64* s_ring = sm + ACT + wp * WARP_U64;   // [NP][66]: [pair][slot*16+dim]
    u64* s_h    = s_ring + NP * ASTR;         // [NP][66]; u in cols 0..15

    // global warp id -> sample base, clamped (tail warps duplicate work)
    long sbase = (long)(blockIdx.x * WPB + wp) * SPW;
    if (sbase > SBMAX) sbase = SBMAX;

    // stage node nx's weights into buf via cp.async (+ commit)
    auto stage = [&](int nx, u64* buf) {
        const bool rt = nx < 4;
        const float *G1, *G2, *G3, *GB1, *GB2, *GB3;
        if (rt) {
            G1 = w_r1 + nx * 1024; G2 = w_r2 + nx * 4096; G3 = w_r3 + nx * 1024;
            GB1 = b_r1 + nx * 64; GB2 = b_r2 + nx * 64; GB3 = b_r3 + nx * 16;
        } else {
            const int j = nx - 4;
            G1 = w_i1 + j * 5120; G2 = w_i2 + j * 4096; G3 = w_i3 + j * 1024;
            GB1 = b_i1 + j * 64; GB2 = b_i2 + j * 64; GB3 = b_i3 + j * 16;
        }
        const u32 base = (u32)__cvta_generic_to_shared(buf);
        const int c1 = rt ? 256 : 1280;
        for (int i = tid; i < c1; i += TPB)   cpa16(base + i * 16, G1 + i * 4);
        for (int i = tid; i < 1024; i += TPB) cpa16(base + BW2 + i * 16, G2 + i * 4);
        for (int i = tid; i < 256; i += TPB)  cpa16(base + BW3 + i * 16, G3 + i * 4);
        if (tid < 16)                   cpa16(base + BB1 + tid * 16, GB1 + tid * 4);
        else if (tid >= 32 && tid < 48) cpa16(base + BB2 + (tid - 32) * 16, GB2 + (tid - 32) * 4);
        else if (tid >= 64 && tid < 68) cpa16(base + BB3 + (tid - 64) * 16, GB3 + (tid - 64) * 4);
        asm volatile("cp.async.commit_group;" ::: "memory");
    };

    // u prefetch registers: lane l (< SPW) = sample sbase+l, 16 dims
    float4 pu0, pu1, pu2, pu3;
    auto ldu = [&](int nx) {
        if (l < SPW) {
            const float4* up =
                (const float4*)(u + (sbase + l) * (NNODES * 16) + nx * 16);
            pu0 = up[0]; pu1 = up[1]; pu2 = up[2]; pu3 = up[3];
        }
    };

    // prologue
    stage(0, sm);
    ldu(0);

    u64 acc0[NP], acc1[NP];

    for (int node = 0; node < NNODES; ++node) {
        u64* wb = sm + (node & 1) * BUFSZ;
        const float* w1 = (const float*)(wb);
        const float* w2 = (const float*)(wb + 2560);
        const float* w3 = (const float*)(wb + 4608);
        const float* b1 = (const float*)(wb + 5120);
        const float* b2 = (const float*)(wb + 5152);
        const float* b3 = (const float*)(wb + 5184);

        asm volatile("cp.async.wait_group 0;" ::: "memory");
        __syncthreads();   // weights ready; prev node's reads of other buf done

        if (node + 1 < NNODES)
            stage(node + 1, sm + ((node + 1) & 1) * BUFSZ);

        // ---- store prefetched u into h cols 0..15 ----
        if (l < SPW) {
            float* inf = (float*)(s_h + (l >> 1) * ASTR);
            const int c = l & 1;
            float uu[16] = {pu0.x, pu0.y, pu0.z, pu0.w,
                            pu1.x, pu1.y, pu1.z, pu1.w,
                            pu2.x, pu2.y, pu2.z, pu2.w,
                            pu3.x, pu3.y, pu3.z, pu3.w};
            #pragma unroll
            for (int dd = 0; dd < 16; ++dd) inf[dd * 2 + c] = uu[dd];
        }
        __syncwarp();

        // R2/R8 inner block: weights (lane's cols 2l,2l+1), broadcast acts.
        auto mm = [&](const float* W, const u64* act, int kcount) {
            #pragma unroll 1
            for (int kk = 0; kk < kcount; kk += 2) {
                float2 wa = *(const float2*)(W + kk * 64 + 2 * l);
                float2 wb2 = *(const float2*)(W + (kk + 1) * 64 + 2 * l);
                const u64 A0 = dup2(wa.x), A1 = dup2(wa.y);
                const u64 B0 = dup2(wb2.x), B1 = dup2(wb2.y);
                #pragma unroll
                for (int p = 0; p < NP; ++p) {
                    ulonglong2 xx = *(const ulonglong2*)(act + p * ASTR + kk);
                    acc0[p] = fma2(xx.x, A0, acc0[p]);
                    acc0[p] = fma2(xx.y, B0, acc0[p]);
                    acc1[p] = fma2(xx.x, A1, acc1[p]);
                    acc1[p] = fma2(xx.y, B1, acc1[p]);
                }
            }
        };

        auto relu_store = [&]() {
            #pragma unroll
            for (int p = 0; p < NP; ++p) {
                ulonglong2 r;
                r.x = relu2(acc0[p]); r.y = relu2(acc1[p]);
                *(ulonglong2*)(s_h + p * ASTR + 2 * l) = r;
            }
        };

        // ---- layer 1 ----
        {
            float2 bb = *(const float2*)(b1 + 2 * l);
            const u64 d0 = dup2(bb.x), d1 = dup2(bb.y);
            #pragma unroll
            for (int p = 0; p < NP; ++p) { acc0[p] = d0; acc1[p] = d1; }
        }
        if (node >= 4) {
            #pragma unroll 1
            for (int q = 0; q < 4; ++q)
                mm(w1 + (q * 16) * 64, s_ring + ((node + q) & 3) * 16, 16);
            mm(w1 + 64 * 64, s_h, 16);       // u part (h cols 0..15)
        } else {
            mm(w1, s_h, 16);
        }
        __syncwarp();     // u reads done before relu_store overwrites cols 0..15
        relu_store();
        __syncwarp();

        // prefetch next node's u (covered by layers 2+3)
        if (node + 1 < NNODES) ldu(node + 1);

        // ---- layer 2 (in-place h) ----
        {
            float2 bb = *(const float2*)(b2 + 2 * l);
            const u64 d0 = dup2(bb.x), d1 = dup2(bb.y);
            #pragma unroll
            for (int p = 0; p < NP; ++p) { acc0[p] = d0; acc1[p] = d1; }
        }
        mm(w2, s_h, 64);
        __syncwarp();     // all lanes done reading old h
        relu_store();
        __syncwarp();

        // ---- layer 3: lane (q8,g) -> dims (2q8,2q8+1), pairs 4g..4g+3
        //      (pp clamped to NP-1; duplicate compute/stores are identical) ----
        u64 c0[4], c1[4];
        {
            const u64 d0 = dup2(b3[2 * q8]), d1 = dup2(b3[2 * q8 + 1]);
            #pragma unroll
            for (int pl = 0; pl < 4; ++pl) { c0[pl] = d0; c1[pl] = d1; }
        }
        int ppi[4];
        #pragma unroll
        for (int pl = 0; pl < 4; ++pl) {
            int pp = 4 * g + pl;
            ppi[pl] = pp > (NP - 1) ? (NP - 1) : pp;
        }
        #pragma unroll 1
        for (int kk = 0; kk < 64; kk += 2) {
            float2 wa = *(const float2*)(w3 + kk * 16 + 2 * q8);
            float2 wb3 = *(const float2*)(w3 + (kk + 1) * 16 + 2 * q8);
            const u64 A0 = dup2(wa.x), A1 = dup2(wa.y);
            const u64 B0 = dup2(wb3.x), B1 = dup2(wb3.y);
            #pragma unroll
            for (int pl = 0; pl < 4; ++pl) {
                ulonglong2 xx =
                    *(const ulonglong2*)(s_h + ppi[pl] * ASTR + kk);
                c0[pl] = fma2(xx.x, A0, c0[pl]);
                c0[pl] = fma2(xx.y, B0, c0[pl]);
                c1[pl] = fma2(xx.x, A1, c1[pl]);
                c1[pl] = fma2(xx.y, B1, c1[pl]);
            }
        }

        // ---- emit: logits to gmem + thresholded ring bits ----
        const int slot = (node & 3) * 16;
        #pragma unroll
        for (int pl = 0; pl < 4; ++pl) {
            const int p = ppi[pl];
            const long s0 = sbase + 2 * p;
            float v00, v01, v10, v11;
            unpk(c0[pl], v00, v01);   // dim 2q8,  samples (2p, 2p+1)
            unpk(c1[pl], v10, v11);   // dim 2q8+1
            float2* o0 = (float2*)(out + s0 * (NNODES * 16) + node * 16 + 2 * q8);
            float2* o1 = (float2*)((float*)o0 + NNODES * 16);
            *o0 = make_float2(v00, v10);
            *o1 = make_float2(v01, v11);
            s_ring[p * ASTR + slot + 2 * q8] =
                pk(v00 > 0.5f ? 1.0f : 0.0f, v01 > 0.5f ? 1.0f : 0.0f);
            s_ring[p * ASTR + slot + 2 * q8 + 1] =
                pk(v10 > 0.5f ? 1.0f : 0.0f, v11 > 0.5f ? 1.0f : 0.0f);
        }
        __syncwarp();   // ring visible to whole warp before next node's layer 1
    }
}

extern "C" void kernel_launch(void* const* d_in, const int* in_sizes, int n_in,
                              void* d_out, int out_size) {
    (void)in_sizes; (void)n_in; (void)out_size;
    cudaFuncSetAttribute(ncm_kernel, cudaFuncAttributeMaxDynamicSharedMemorySize,
                         SMEM_BYTES);
    ncm_kernel<<<NBLK, TPB, SMEM_BYTES>>>(
        (const float*)d_in[0],
        (const float*)d_in[1], (const float*)d_in[2],
        (const float*)d_in[3], (const float*)d_in[4],
        (const float*)d_in[5], (const float*)d_in[6],
        (const float*)d_in[7], (const float*)d_in[8],
        (const float*)d_in[9], (const float*)d_in[10],
        (const float*)d_in[11], (const float*)d_in[12],
        (float*)d_out);
}

// round 11
// speedup vs baseline: 1.0288x; 1.0288x over previous
#include <cuda_runtime.h>

// NCM R11: 4-col/lane tile in the R9 chassis. Warp = 2 x 16-lane groups,
// group owns 5 sample-pairs (20 samples/warp), lane owns cols 4t..4t+3
// (L1/L2) and col t (L3). Act buffers bank-disjoint across groups.
// cp.async double-buffered weights, u prefetch, 1 barrier/node.
// Grid 148 x TPB 384 (3 warps/SMSP).

#define TPB    384
#define NBLK   148
#define NNODES 32
#define WPB    12
#define NPG    5           // pairs per 16-lane group
#define SPW    20          // samples per warp
#define SBMAX  (32768 - SPW)

typedef unsigned long long u64;
typedef unsigned int u32;

__device__ __forceinline__ u64 fma2(u64 a, u64 b, u64 c) {
    u64 d; asm("fma.rn.f32x2 %0,%1,%2,%3;" : "=l"(d) : "l"(a), "l"(b), "l"(c));
    return d;
}
__device__ __forceinline__ u64 dup2(float x) {
    u64 d; asm("mov.b64 %0,{%1,%1};" : "=l"(d) : "f"(x)); return d;
}
__device__ __forceinline__ void unpk(u64 a, float& lo, float& hi) {
    asm("mov.b64 {%0,%1},%2;" : "=f"(lo), "=f"(hi) : "l"(a));
}
__device__ __forceinline__ u64 pk(float lo, float hi) {
    u64 d; asm("mov.b64 %0,{%1,%2};" : "=l"(d) : "f"(lo), "f"(hi)); return d;
}
__device__ __forceinline__ u64 relu2(u64 a) {
    float lo, hi; unpk(a, lo, hi);
    return pk(fmaxf(lo, 0.0f), fmaxf(hi, 0.0f));
}
__device__ __forceinline__ void cpa16(u32 dst, const float* src) {
    asm volatile("cp.async.cg.shared.global [%0], [%1], 16;"
                 :: "r"(dst), "l"(src));
}

// weight buffer (u64 units): W1 0 | W2 2560 | W3 4608 | B1 5120 | B2 5152 | B3 5184
#define BUFSZ 5192
#define BW2 20480
#define BW3 36864
#define BB1 40960
#define BB2 41216
#define BB3 41472
#define ACT (2 * BUFSZ)                 // 10384 u64
// per-warp acts (u64):
//   IN: grp0 [5][80] | pad8 | grp1 [5][80]   (cols 0..63 ring, 64..79 u)
//   H : grp0 [5][64] | pad8 | grp1 [5][64]
#define IN_STR 80
#define IN_GOFF 408        // 2*408 mod 32 == 16 -> disjoint bank halves
#define H_STR  64
#define H_GOFF 328         // 2*328 mod 32 == 16
#define IN_TOT (IN_GOFF + 5 * IN_STR)   // 808
#define H_TOT  (H_GOFF + 5 * H_STR)     // 648
#define WARP_U64 (IN_TOT + H_TOT)       // 1456
#define SMEM_BYTES ((ACT + WPB * WARP_U64) * 8)   // 222848

__global__ void __launch_bounds__(TPB, 1) ncm_kernel(
    const float* __restrict__ u,
    const float* __restrict__ w_r1, const float* __restrict__ b_r1,
    const float* __restrict__ w_r2, const float* __restrict__ b_r2,
    const float* __restrict__ w_r3, const float* __restrict__ b_r3,
    const float* __restrict__ w_i1, const float* __restrict__ b_i1,
    const float* __restrict__ w_i2, const float* __restrict__ b_i2,
    const float* __restrict__ w_i3, const float* __restrict__ b_i3,
    float* __restrict__ out)
{
    extern __shared__ u64 sm[];

    const int tid = threadIdx.x;
    const int wp = tid >> 5, l = tid & 31;
    const int grp = l >> 4;        // 16-lane group
    const int t = l & 15;          // lane-in-group: cols 4t..4t+3 (L1/L2), t (L3)

    u64* warp_u = sm + ACT + wp * WARP_U64;
    u64* s_in_g = warp_u + grp * IN_GOFF;           // [5][80]
    u64* s_h_g  = warp_u + IN_TOT + grp * H_GOFF;   // [5][64]

    long sbase = (long)(blockIdx.x * WPB + wp) * SPW;
    if (sbase > SBMAX) sbase = SBMAX;

    // stage node nx's weights via cp.async (+ commit)
    auto stage = [&](int nx, u64* buf) {
        const bool rt = nx < 4;
        const float *G1, *G2, *G3, *GB1, *GB2, *GB3;
        if (rt) {
            G1 = w_r1 + nx * 1024; G2 = w_r2 + nx * 4096; G3 = w_r3 + nx * 1024;
            GB1 = b_r1 + nx * 64; GB2 = b_r2 + nx * 64; GB3 = b_r3 + nx * 16;
        } else {
            const int j = nx - 4;
            G1 = w_i1 + j * 5120; G2 = w_i2 + j * 4096; G3 = w_i3 + j * 1024;
            GB1 = b_i1 + j * 64; GB2 = b_i2 + j * 64; GB3 = b_i3 + j * 16;
        }
        const u32 base = (u32)__cvta_generic_to_shared(buf);
        const int c1 = rt ? 256 : 1280;
        for (int i = tid; i < c1; i += TPB)   cpa16(base + i * 16, G1 + i * 4);
        for (int i = tid; i < 1024; i += TPB) cpa16(base + BW2 + i * 16, G2 + i * 4);
        for (int i = tid; i < 256; i += TPB)  cpa16(base + BW3 + i * 16, G3 + i * 4);
        if (tid < 16)                   cpa16(base + BB1 + tid * 16, GB1 + tid * 4);
        else if (tid >= 32 && tid < 48) cpa16(base + BB2 + (tid - 32) * 16, GB2 + (tid - 32) * 4);
        else if (tid >= 64 && tid < 68) cpa16(base + BB3 + (tid - 64) * 16, GB3 + (tid - 64) * 4);
        asm volatile("cp.async.commit_group;" ::: "memory");
    };

    // u prefetch: lane l (< SPW) = sample sbase+l
    float4 pu0, pu1, pu2, pu3;
    auto ldu = [&](int nx) {
        if (l < SPW) {
            const float4* up =
                (const float4*)(u + (sbase + l) * (NNODES * 16) + nx * 16);
            pu0 = up[0]; pu1 = up[1]; pu2 = up[2]; pu3 = up[3];
        }
    };

    stage(0, sm);
    ldu(0);

    u64 acc[4 * NPG];   // [pair][col] = acc[p*4+c]

    for (int node = 0; node < NNODES; ++node) {
        u64* wb = sm + (node & 1) * BUFSZ;
        const float* w1 = (const float*)(wb);
        const float* w2 = (const float*)(wb + 2560);
        const float* w3 = (const float*)(wb + 4608);
        const float* b1 = (const float*)(wb + 5120);
        const float* b2 = (const float*)(wb + 5152);
        const float* b3 = (const float*)(wb + 5184);

        asm volatile("cp.async.wait_group 0;" ::: "memory");
        __syncthreads();

        if (node + 1 < NNODES)
            stage(node + 1, sm + ((node + 1) & 1) * BUFSZ);

        // ---- store prefetched u: sample's pair lives in its group's region ----
        if (l < SPW) {
            const int pg = l >> 1;                 // global pair 0..9
            const int gs = pg / NPG, ps = pg % NPG;
            const int c = l & 1;
            float* inf = (float*)(warp_u + gs * IN_GOFF + ps * IN_STR + 64);
            float uu[16] = {pu0.x, pu0.y, pu0.z, pu0.w,
                            pu1.x, pu1.y, pu1.z, pu1.w,
                            pu2.x, pu2.y, pu2.z, pu2.w,
                            pu3.x, pu3.y, pu3.z, pu3.w};
            #pragma unroll
            for (int dd = 0; dd < 16; ++dd) inf[dd * 2 + c] = uu[dd];
        }
        __syncwarp();

        // inner block: W rows (cols 4t..4t+3), broadcast acts per group.
        auto mm = [&](const float* W, const u64* act, int stride, int kcount) {
            #pragma unroll 1
            for (int kk = 0; kk < kcount; kk += 2) {
                float4 wa = *(const float4*)(W + kk * 64 + 4 * t);
                float4 wbv = *(const float4*)(W + (kk + 1) * 64 + 4 * t);
                const u64 A0 = dup2(wa.x), A1 = dup2(wa.y),
                          A2 = dup2(wa.z), A3 = dup2(wa.w);
                const u64 B0 = dup2(wbv.x), B1 = dup2(wbv.y),
                          B2 = dup2(wbv.z), B3 = dup2(wbv.w);
                #pragma unroll
                for (int p = 0; p < NPG; ++p) {
                    ulonglong2 xx = *(const ulonglong2*)(act + p * stride + kk);
                    acc[p * 4 + 0] = fma2(xx.x, A0, acc[p * 4 + 0]);
                    acc[p * 4 + 1] = fma2(xx.x, A1, acc[p * 4 + 1]);
                    acc[p * 4 + 2] = fma2(xx.x, A2, acc[p * 4 + 2]);
                    acc[p * 4 + 3] = fma2(xx.x, A3, acc[p * 4 + 3]);
                    acc[p * 4 + 0] = fma2(xx.y, B0, acc[p * 4 + 0]);
                    acc[p * 4 + 1] = fma2(xx.y, B1, acc[p * 4 + 1]);
                    acc[p * 4 + 2] = fma2(xx.y, B2, acc[p * 4 + 2]);
                    acc[p * 4 + 3] = fma2(xx.y, B3, acc[p * 4 + 3]);
                }
            }
        };

        auto relu_store = [&]() {
            #pragma unroll
            for (int p = 0; p < NPG; ++p) {
                ulonglong2 r0, r1;
                r0.x = relu2(acc[p * 4 + 0]); r0.y = relu2(acc[p * 4 + 1]);
                r1.x = relu2(acc[p * 4 + 2]); r1.y = relu2(acc[p * 4 + 3]);
                *(ulonglong2*)(s_h_g + p * H_STR + 4 * t)     = r0;
                *(ulonglong2*)(s_h_g + p * H_STR + 4 * t + 2) = r1;
            }
        };

        // ---- layer 1 ----
        {
            float4 bb = *(const float4*)(b1 + 4 * t);
            const u64 i0 = dup2(bb.x), i1 = dup2(bb.y),
                      i2 = dup2(bb.z), i3 = dup2(bb.w);
            #pragma unroll
            for (int p = 0; p < NPG; ++p) {
                acc[p * 4 + 0] = i0; acc[p * 4 + 1] = i1;
                acc[p * 4 + 2] = i2; acc[p * 4 + 3] = i3;
            }
        }
        if (node >= 4) {
            #pragma unroll 1
            for (int q = 0; q < 4; ++q)
                mm(w1 + (q * 16) * 64, s_in_g + ((node + q) & 3) * 16, IN_STR, 16);
            mm(w1 + 64 * 64, s_in_g + 64, IN_STR, 16);   // u cols 64..79
        } else {
            mm(w1, s_in_g + 64, IN_STR, 16);
        }
        relu_store();
        __syncwarp();

        if (node + 1 < NNODES) ldu(node + 1);   // covered by layers 2+3

        // ---- layer 2 (in-place h) ----
        {
            float4 bb = *(const float4*)(b2 + 4 * t);
            const u64 i0 = dup2(bb.x), i1 = dup2(bb.y),
                      i2 = dup2(bb.z), i3 = dup2(bb.w);
            #pragma unroll
            for (int p = 0; p < NPG; ++p) {
                acc[p * 4 + 0] = i0; acc[p * 4 + 1] = i1;
                acc[p * 4 + 2] = i2; acc[p * 4 + 3] = i3;
            }
        }
        mm(w2, s_h_g, H_STR, 64);
        __syncwarp();
        relu_store();
        __syncwarp();

        // ---- layer 3: lane t -> dim t; group's 5 pairs ----
        u64 c3[NPG];
        {
            const u64 bt = dup2(b3[t]);
            #pragma unroll
            for (int p = 0; p < NPG; ++p) c3[p] = bt;
        }
        #pragma unroll 1
        for (int kk = 0; kk < 64; kk += 2) {
            const u64 A = dup2(w3[kk * 16 + t]);
            const u64 B = dup2(w3[(kk + 1) * 16 + t]);
            #pragma unroll
            for (int p = 0; p < NPG; ++p) {
                ulonglong2 xx = *(const ulonglong2*)(s_h_g + p * H_STR + kk);
                c3[p] = fma2(xx.x, A, c3[p]);
                c3[p] = fma2(xx.y, B, c3[p]);
            }
        }

        // ---- emit: logits + thresholded ring bits ----
        const int slot = (node & 3) * 16;
        #pragma unroll
        for (int p = 0; p < NPG; ++p) {
            const long s0 = sbase + 2 * (grp * NPG + p);
            float v0, v1; unpk(c3[p], v0, v1);
            out[s0 * (NNODES * 16) + node * 16 + t] = v0;
            out[(s0 + 1) * (NNODES * 16) + node * 16 + t] = v1;
            s_in_g[p * IN_STR + slot + t] =
                pk(v0 > 0.5f ? 1.0f : 0.0f, v1 > 0.5f ? 1.0f : 0.0f);
        }
        __syncwarp();
    }
}

extern "C" void kernel_launch(void* const* d_in, const int* in_sizes, int n_in,
                              void* d_out, int out_size) {
    (void)in_sizes; (void)n_in; (void)out_size;
    cudaFuncSetAttribute(ncm_kernel, cudaFuncAttributeMaxDynamicSharedMemorySize,
                         SMEM_BYTES);
    ncm_kernel<<<NBLK, TPB, SMEM_BYTES>>>(
        (const float*)d_in[0],
        (const float*)d_in[1], (const float*)d_in[2],
        (const float*)d_in[3], (const float*)d_in[4],
        (const float*)d_in[5], (const float*)d_in[6],
        (const float*)d_in[7], (const float*)d_in[8],
        (const float*)d_in[9], (const float*)d_in[10],
        (const float*)d_in[11], (const float*)d_in[12],
        (float*)d_out);
}

// round 17
// speedup vs baseline: 1.0759x; 1.0458x over previous
#include <cuda_runtime.h>

// NCM R17 == R9 byte-for-byte (the 472.3us PASS artifact). Re-verification
// run: four statically-safe variants (R12/R13/R15/R16) of this kernel all
// crashed; this tests latent-timing-fault vs environment-shift hypotheses.
// Grid 148 (one CTA per SM), warp tile 28 samples = 14 f32x2 pairs; tail
// warps clamp sbase and duplicate-compute (identical racing writes, benign).
// cp.async double-buffered weights, u prefetch, 1 barrier/node.

#define TPB    256
#define NBLK   148
#define NNODES 32
#define NP     14          // sample-pairs per warp
#define SPW    28          // samples per warp
#define SBMAX  (32768 - SPW)

typedef unsigned long long u64;
typedef unsigned int u32;

__device__ __forceinline__ u64 fma2(u64 a, u64 b, u64 c) {
    u64 d; asm("fma.rn.f32x2 %0,%1,%2,%3;" : "=l"(d) : "l"(a), "l"(b), "l"(c));
    return d;
}
__device__ __forceinline__ u64 dup2(float x) {
    u64 d; asm("mov.b64 %0,{%1,%1};" : "=l"(d) : "f"(x)); return d;
}
__device__ __forceinline__ void unpk(u64 a, float& lo, float& hi) {
    asm("mov.b64 {%0,%1},%2;" : "=f"(lo), "=f"(hi) : "l"(a));
}
__device__ __forceinline__ u64 pk(float lo, float hi) {
    u64 d; asm("mov.b64 %0,{%1,%2};" : "=l"(d) : "f"(lo), "f"(hi)); return d;
}
__device__ __forceinline__ u64 relu2(u64 a) {
    float lo, hi; unpk(a, lo, hi);
    return pk(fmaxf(lo, 0.0f), fmaxf(hi, 0.0f));
}
__device__ __forceinline__ void cpa16(u32 dst, const float* src) {
    asm volatile("cp.async.cg.shared.global [%0], [%1], 16;"
                 :: "r"(dst), "l"(src));
}

// per-buffer u64 offsets: W1 0 | W2 2560 | W3 4608 | B1 5120 | B2 5152 | B3 5184
#define BUFSZ 5192
// byte offsets inside buffer
#define BW2 20480
#define BW3 36864
#define BB1 40960
#define BB2 41216
#define BB3 41472
#define ACT (2 * BUFSZ)                 // 10384 u64
// per-warp acts: ring u64[NP][66] | h u64[NP][66] (u aliased into h cols 0..15)
#define ASTR 66
#define WARP_U64 (2 * NP * ASTR)        // 1848
#define SMEM_BYTES ((ACT + 8 * WARP_U64) * 8)   // 201344

__global__ void __launch_bounds__(TPB, 1) ncm_kernel(
    const float* __restrict__ u,
    const float* __restrict__ w_r1, const float* __restrict__ b_r1,
    const float* __restrict__ w_r2, const float* __restrict__ b_r2,
    const float* __restrict__ w_r3, const float* __restrict__ b_r3,
    const float* __restrict__ w_i1, const float* __restrict__ b_i1,
    const float* __restrict__ w_i2, const float* __restrict__ b_i2,
    const float* __restrict__ w_i3, const float* __restrict__ b_i3,
    float* __restrict__ out)
{
    extern __shared__ u64 sm[];

    const int tid = threadIdx.x;
    const int wp = tid >> 5, l = tid & 31;
    const int q8 = l & 7;    // L3: output dims (2q8, 2q8+1)
    const int g  = l >> 3;   // L3: pairs 4g..4g+3 (clamped to 13)

    u64* s_ring = sm + ACT + wp * WARP_U64;   // [NP][66]: [pair][slot*16+dim]
    u64* s_h    = s_ring + NP * ASTR;         // [NP][66]; u in cols 0..15

    // global warp id -> sample base, clamped (tail warps duplicate work)
    long sbase = (long)(blockIdx.x * 8 + wp) * SPW;
    if (sbase > SBMAX) sbase = SBMAX;

    // stage node nx's weights into buf via cp.async (+ commit)
    auto stage = [&](int nx, u64* buf) {
        const bool rt = nx < 4;
        const float *G1, *G2, *G3, *GB1, *GB2, *GB3;
        if (rt) {
            G1 = w_r1 + nx * 1024; G2 = w_r2 + nx * 4096; G3 = w_r3 + nx * 1024;
            GB1 = b_r1 + nx * 64; GB2 = b_r2 + nx * 64; GB3 = b_r3 + nx * 16;
        } else {
            const int j = nx - 4;
            G1 = w_i1 + j * 5120; G2 = w_i2 + j * 4096; G3 = w_i3 + j * 1024;
            GB1 = b_i1 + j * 64; GB2 = b_i2 + j * 64; GB3 = b_i3 + j * 16;
        }
        const u32 base = (u32)__cvta_generic_to_shared(buf);
        const int c1 = rt ? 256 : 1280;
        for (int i = tid; i < c1; i += TPB)   cpa16(base + i * 16, G1 + i * 4);
        for (int i = tid; i < 1024; i += TPB) cpa16(base + BW2 + i * 16, G2 + i * 4);
        for (int i = tid; i < 256; i += TPB)  cpa16(base + BW3 + i * 16, G3 + i * 4);
        if (tid < 16)                   cpa16(base + BB1 + tid * 16, GB1 + tid * 4);
        else if (tid >= 32 && tid < 48) cpa16(base + BB2 + (tid - 32) * 16, GB2 + (tid - 32) * 4);
        else if (tid >= 64 && tid < 68) cpa16(base + BB3 + (tid - 64) * 16, GB3 + (tid - 64) * 4);
        asm volatile("cp.async.commit_group;" ::: "memory");
    };

    // u prefetch registers: lane l (< SPW) = sample sbase+l, 16 dims
    float4 pu0, pu1, pu2, pu3;
    auto ldu = [&](int nx) {
        if (l < SPW) {
            const float4* up =
                (const float4*)(u + (sbase + l) * (NNODES * 16) + nx * 16);
            pu0 = up[0]; pu1 = up[1]; pu2 = up[2]; pu3 = up[3];
        }
    };

    // prologue
    stage(0, sm);
    ldu(0);

    u64 acc0[NP], acc1[NP];

    for (int node = 0; node < NNODES; ++node) {
        u64* wb = sm + (node & 1) * BUFSZ;
        const float* w1 = (const float*)(wb);
        const float* w2 = (const float*)(wb + 2560);
        const float* w3 = (const float*)(wb + 4608);
        const float* b1 = (const float*)(wb + 5120);
        const float* b2 = (const float*)(wb + 5152);
        const float* b3 = (const float*)(wb + 5184);

        asm volatile("cp.async.wait_group 0;" ::: "memory");
        __syncthreads();   // weights ready; prev node's reads of other buf done

        if (node + 1 < NNODES)
            stage(node + 1, sm + ((node + 1) & 1) * BUFSZ);

        // ---- store prefetched u into h cols 0..15 ----
        if (l < SPW) {
            float* inf = (float*)(s_h + (l >> 1) * ASTR);
            const int c = l & 1;
            float uu[16] = {pu0.x, pu0.y, pu0.z, pu0.w,
                            pu1.x, pu1.y, pu1.z, pu1.w,
                            pu2.x, pu2.y, pu2.z, pu2.w,
                            pu3.x, pu3.y, pu3.z, pu3.w};
            #pragma unroll
            for (int dd = 0; dd < 16; ++dd) inf[dd * 2 + c] = uu[dd];
        }
        __syncwarp();

        // R2/R8 inner block: weights (lane's cols 2l,2l+1), broadcast acts.
        auto mm = [&](const float* W, const u64* act, int kcount) {
            #pragma unroll 1
            for (int kk = 0; kk < kcount; kk += 2) {
                float2 wa = *(const float2*)(W + kk * 64 + 2 * l);
                float2 wb2 = *(const float2*)(W + (kk + 1) * 64 + 2 * l);
                const u64 A0 = dup2(wa.x), A1 = dup2(wa.y);
                const u64 B0 = dup2(wb2.x), B1 = dup2(wb2.y);
                #pragma unroll
                for (int p = 0; p < NP; ++p) {
                    ulonglong2 xx = *(const ulonglong2*)(act + p * ASTR + kk);
                    acc0[p] = fma2(xx.x, A0, acc0[p]);
                    acc0[p] = fma2(xx.y, B0, acc0[p]);
                    acc1[p] = fma2(xx.x, A1, acc1[p]);
                    acc1[p] = fma2(xx.y, B1, acc1[p]);
                }
            }
        };

        auto relu_store = [&]() {
            #pragma unroll
            for (int p = 0; p < NP; ++p) {
                ulonglong2 r;
                r.x = relu2(acc0[p]); r.y = relu2(acc1[p]);
                *(ulonglong2*)(s_h + p * ASTR + 2 * l) = r;
            }
        };

        // ---- layer 1 ----
        {
            float2 bb = *(const float2*)(b1 + 2 * l);
            const u64 d0 = dup2(bb.x), d1 = dup2(bb.y);
            #pragma unroll
            for (int p = 0; p < NP; ++p) { acc0[p] = d0; acc1[p] = d1; }
        }
        if (node >= 4) {
            #pragma unroll 1
            for (int q = 0; q < 4; ++q)
                mm(w1 + (q * 16) * 64, s_ring + ((node + q) & 3) * 16, 16);
            mm(w1 + 64 * 64, s_h, 16);
        } else {
            mm(w1, s_h, 16);
        }
        __syncwarp();
        relu_store();
        __syncwarp();

        if (node + 1 < NNODES) ldu(node + 1);

        // ---- layer 2 (in-place h) ----
        {
            float2 bb = *(const float2*)(b2 + 2 * l);
            const u64 d0 = dup2(bb.x), d1 = dup2(bb.y);
            #pragma unroll
            for (int p = 0; p < NP; ++p) { acc0[p] = d0; acc1[p] = d1; }
        }
        mm(w2, s_h, 64);
        __syncwarp();
        relu_store();
        __syncwarp();

        // ---- layer 3: lane (q8,g) -> dims (2q8,2q8+1), pairs 4g..4g+3
        //      (pp clamped to NP-1; duplicate compute/stores are identical) ----
        u64 c0[4], c1[4];
        {
            const u64 d0 = dup2(b3[2 * q8]), d1 = dup2(b3[2 * q8 + 1]);
            #pragma unroll
            for (int pl = 0; pl < 4; ++pl) { c0[pl] = d0; c1[pl] = d1; }
        }
        int ppi[4];
        #pragma unroll
        for (int pl = 0; pl < 4; ++pl) {
            int pp = 4 * g + pl;
            ppi[pl] = pp > (NP - 1) ? (NP - 1) : pp;
        }
        #pragma unroll 1
        for (int kk = 0; kk < 64; kk += 2) {
            float2 wa = *(const float2*)(w3 + kk * 16 + 2 * q8);
            float2 wb3 = *(const float2*)(w3 + (kk + 1) * 16 + 2 * q8);
            const u64 A0 = dup2(wa.x), A1 = dup2(wa.y);
            const u64 B0 = dup2(wb3.x), B1 = dup2(wb3.y);
            #pragma unroll
            for (int pl = 0; pl < 4; ++pl) {
                ulonglong2 xx =
                    *(const ulonglong2*)(s_h + ppi[pl] * ASTR + kk);
                c0[pl] = fma2(xx.x, A0, c0[pl]);
                c0[pl] = fma2(xx.y, B0, c0[pl]);
                c1[pl] = fma2(xx.x, A1, c1[pl]);
                c1[pl] = fma2(xx.y, B1, c1[pl]);
            }
        }

        // ---- emit: logits to gmem + thresholded ring bits ----
        const int slot = (node & 3) * 16;
        #pragma unroll
        for (int pl = 0; pl < 4; ++pl) {
            const int p = ppi[pl];
            const long s0 = sbase + 2 * p;
            float v00, v01, v10, v11;
            unpk(c0[pl], v00, v01);   // dim 2q8,  samples (2p, 2p+1)
            unpk(c1[pl], v10, v11);   // dim 2q8+1
            float2* o0 = (float2*)(out + s0 * (NNODES * 16) + node * 16 + 2 * q8);
            float2* o1 = (float2*)((float*)o0 + NNODES * 16);
            *o0 = make_float2(v00, v10);
            *o1 = make_float2(v01, v11);
            s_ring[p * ASTR + slot + 2 * q8] =
                pk(v00 > 0.5f ? 1.0f : 0.0f, v01 > 0.5f ? 1.0f : 0.0f);
            s_ring[p * ASTR + slot + 2 * q8 + 1] =
                pk(v10 > 0.5f ? 1.0f : 0.0f, v11 > 0.5f ? 1.0f : 0.0f);
        }
        __syncwarp();   // ring visible to whole warp before next node's layer 1
    }
}

extern "C" void kernel_launch(void* const* d_in, const int* in_sizes, int n_in,
                              void* d_out, int out_size) {
    (void)in_sizes; (void)n_in; (void)out_size;
    cudaFuncSetAttribute(ncm_kernel, cudaFuncAttributeMaxDynamicSharedMemorySize,
                         SMEM_BYTES);
    ncm_kernel<<<NBLK, TPB, SMEM_BYTES>>>(
        (const float*)d_in[0],
        (const float*)d_in[1], (const float*)d_in[2],
        (const float*)d_in[3], (const float*)d_in[4],
        (const float*)d_in[5], (const float*)d_in[6],
        (const float*)d_in[7], (const float*)d_in[8],
        (const float*)d_in[9], (const float*)d_in[10],
        (const float*)d_in[11], (const float*)d_in[12],
        (float*)d_out);
}